// round 8
// baseline (speedup 1.0000x reference)
#include <cuda_runtime.h>
#include <cuda_bf16.h>
#include <cstdint>

// ============================================================================
// MultiSimilarityLoss on GB300 (sm_103a; PTX target compute_103 -> no tcgen05;
// mma.sync bf16 HMMA + ldmatrix)
//   R8: fp32->bf16 conversion fused INTO the mainloop (register-staged LDG +
//   cvt + STS), eliminating the 9.5us prep kernel. Upper-triangular 128x128
//   tiles; dual-sided fused epilogue; one __syncthreads per K-chunk.
// ============================================================================

#define N_EMB   4096
#define D_EMB   512
#define MTILE   128
#define NTILE   128
#define KCH     64            // K chunk (64 bf16 = 128B rows, SW128)
#define NCHUNKS (D_EMB / KCH) // 8
#define NTHREADS 256
#define NTB     (N_EMB / MTILE)          // 32
#define NTILES  (NTB * (NTB + 1) / 2)    // 528

// Scratch (no cudaMalloc allowed)
__device__ float g_pos[N_EMB];
__device__ float g_neg[N_EMB];
__device__ int   g_lab[N_EMB];

// smem: labels (1KB) + double-buffered A/B bf16 tiles (4 x 16KB)
#define SM_LABELS  0
#define SM_TILES   1024
#define TILE_BYTES 16384                 // 128 rows x 128B
#define SM_TOTAL   (1024 + 4 * TILE_BYTES)  // 66560

__device__ __forceinline__ uint32_t smem_u32(const void* p) {
    uint32_t a;
    asm("{ .reg .u64 t; cvta.to.shared.u64 t, %1; cvt.u32.u64 %0, t; }" : "=r"(a) : "l"(p));
    return a;
}

__device__ __forceinline__ uint32_t sw128(uint32_t off) {
    return off ^ ((off >> 3) & 0x70);
}

__device__ __forceinline__ void ldsm_x4(uint32_t* r, uint32_t addr) {
    asm volatile("ldmatrix.sync.aligned.m8n8.x4.shared.b16 {%0,%1,%2,%3}, [%4];"
                 : "=r"(r[0]), "=r"(r[1]), "=r"(r[2]), "=r"(r[3]) : "r"(addr));
}

__device__ __forceinline__ void mma16816(float* d, const uint32_t* a, uint32_t b0, uint32_t b1) {
    asm volatile(
        "mma.sync.aligned.m16n8k16.row.col.f32.bf16.bf16.f32 "
        "{%0,%1,%2,%3}, {%4,%5,%6,%7}, {%8,%9}, {%0,%1,%2,%3};"
        : "+f"(d[0]), "+f"(d[1]), "+f"(d[2]), "+f"(d[3])
        : "r"(a[0]), "r"(a[1]), "r"(a[2]), "r"(a[3]), "r"(b0), "r"(b1));
}

__device__ __forceinline__ uint32_t bfpack(float lo, float hi) {
    __nv_bfloat162 t = __floats2bfloat162_rn(lo, hi);
    return *(uint32_t*)&t;
}

__device__ __forceinline__ void sts128(uint32_t addr, uint32_t x, uint32_t y, uint32_t z, uint32_t w) {
    asm volatile("st.shared.v4.b32 [%0], {%1,%2,%3,%4};" :: "r"(addr), "r"(x), "r"(y), "r"(z), "r"(w));
}

// convert 8 floats (2 float4) -> 16B and store swizzled
__device__ __forceinline__ void cvt_sts(uint32_t addr, float4 a, float4 b) {
    sts128(addr, bfpack(a.x, a.y), bfpack(a.z, a.w), bfpack(b.x, b.y), bfpack(b.z, b.w));
}

// ============================================================================
// Kernel 0: init — labels decode (block 0) + zero accumulators  (tiny)
// ============================================================================
__global__ void ms_init(const void* __restrict__ rawlab) {
    int t = threadIdx.x;
    int g = blockIdx.x * blockDim.x + t;
    if (blockIdx.x == 0) {
        __shared__ int s_not64;
        const int* r32 = (const int*)rawlab;
        if (t == 0) s_not64 = 0;
        __syncthreads();
        int nz = 0;
        for (int i = t; i < N_EMB / 2; i += NTHREADS) nz |= r32[2 * i + 1];
        if (nz) atomicOr(&s_not64, 1);
        __syncthreads();
        if (s_not64 == 0) {
            const long long* r64 = (const long long*)rawlab;
            for (int i = t; i < N_EMB; i += NTHREADS) g_lab[i] = (int)r64[i];
        } else {
            for (int i = t; i < N_EMB; i += NTHREADS) g_lab[i] = r32[i];
        }
    }
    if (g < N_EMB) { g_pos[g] = 0.f; g_neg[g] = 0.f; }
    else if (g < 2 * N_EMB) { /* covered above by separate arrays */ }
}

// ============================================================================
// Kernel 1: main — triangular 128x128 tiles; fused fp32->bf16 load path
// ============================================================================
__global__ __launch_bounds__(NTHREADS, 2) void ms_main(const float* __restrict__ emb) {
    extern __shared__ char smem[];
    int* collab = (int*)(smem + SM_LABELS);        // 128 ints
    int* rowlab = (int*)(smem + SM_LABELS + 512);  // 128 ints
    char* tiles = smem + SM_TILES;

    // linear tile id -> (by, bx), bx >= by
    int rem = blockIdx.x;
    int by = 0;
    while (rem >= (NTB - by)) { rem -= (NTB - by); by++; }
    int bx = by + rem;
    const bool isdiag = (bx == by);

    const int tid  = threadIdx.x;
    const int wid  = tid >> 5;
    const int lane = tid & 31;
    const int wm   = wid & 3;
    const int wn   = wid >> 2;
    const int colbase = bx * NTILE;
    const int rowbase = by * MTILE;

    if (tid < 128) collab[tid] = g_lab[colbase + tid];
    else           rowlab[tid - 128] = g_lab[rowbase + tid - 128];

    // conversion-loader mapping: each thread owns row r, half h (32 fp32)
    const int cr = tid >> 1;            // 0..127
    const int chh = tid & 1;            // 0/1 -> fp32 cols [h*32, h*32+32)
    const float* gAf = emb + (size_t)(rowbase + cr) * D_EMB + chh * 32;
    const float* gBf = emb + (size_t)(colbase + cr) * D_EMB + chh * 32;
    // STS base offsets for this thread's 64B within the 128B bf16 row
    uint32_t stsoff[4];
    #pragma unroll
    for (int q = 0; q < 4; q++)
        stsoff[q] = sw128((uint32_t)(cr * 128 + chh * 64 + q * 16));

    uint32_t bufAu[2], bufBu[2];
    bufAu[0] = smem_u32(tiles);
    bufBu[0] = bufAu[0] + TILE_BYTES;
    bufAu[1] = bufBu[0] + TILE_BYTES;
    bufBu[1] = bufAu[1] + TILE_BYTES;

    float4 rA[8], rB[8];

    // ---- prologue: chunk 0 (A and B), then preload A-batch of chunk 1 ----
    #pragma unroll
    for (int i = 0; i < 8; i++) rA[i] = ((const float4*)(gAf))[i];
    if (!isdiag) {
        #pragma unroll
        for (int i = 0; i < 8; i++) rB[i] = ((const float4*)(gBf))[i];
    }
    #pragma unroll
    for (int q = 0; q < 4; q++) cvt_sts(bufAu[0] + stsoff[q], rA[2 * q], rA[2 * q + 1]);
    if (!isdiag) {
        #pragma unroll
        for (int q = 0; q < 4; q++) cvt_sts(bufBu[0] + stsoff[q], rB[2 * q], rB[2 * q + 1]);
    }
    #pragma unroll
    for (int i = 0; i < 8; i++) rA[i] = ((const float4*)(gAf + KCH))[i];
    __syncthreads();

    float d[2][8][4];
    #pragma unroll
    for (int mt = 0; mt < 2; mt++)
        #pragma unroll
        for (int nt = 0; nt < 8; nt++)
            #pragma unroll
            for (int r = 0; r < 4; r++) d[mt][nt][r] = 0.f;

    const int lrow = (lane & 7) + ((lane >> 3) & 1) * 8;
    const int lkh  = (lane >> 4) * 16;

    for (int c = 0; c < NCHUNKS; c++) {
        int nb = (c + 1) & 1;
        if (c + 1 < NCHUNKS) {
            // A(c+1) already in rA: convert+store, then launch B(c+1) loads
            #pragma unroll
            for (int q = 0; q < 4; q++) cvt_sts(bufAu[nb] + stsoff[q], rA[2 * q], rA[2 * q + 1]);
            if (!isdiag) {
                #pragma unroll
                for (int i = 0; i < 8; i++) rB[i] = ((const float4*)(gBf + (c + 1) * KCH))[i];
            }
        }

        uint32_t abase = bufAu[c & 1];
        uint32_t bbase = isdiag ? abase : bufBu[c & 1];

        #pragma unroll
        for (int s = 0; s < 4; s++) {
            uint32_t kb = s * 32;
            uint32_t a[2][4];
            #pragma unroll
            for (int mt = 0; mt < 2; mt++) {
                int row = wm * 32 + mt * 16 + lrow;
                ldsm_x4(a[mt], abase + sw128(row * 128 + kb + lkh));
            }
            uint32_t bq[4][4];
            #pragma unroll
            for (int nt2 = 0; nt2 < 4; nt2++) {
                int row = wn * 64 + nt2 * 16 + lrow;
                ldsm_x4(bq[nt2], bbase + sw128(row * 128 + kb + lkh));
            }
            #pragma unroll
            for (int mt = 0; mt < 2; mt++)
                #pragma unroll
                for (int nt = 0; nt < 8; nt++) {
                    int nt2 = nt >> 1, odd = nt & 1;
                    mma16816(d[mt][nt], a[mt], bq[nt2][odd], bq[nt2][odd + 2]);
                }
        }

        if (c + 1 < NCHUNKS) {
            // B(c+1) landed during the MMA phase: convert+store
            if (!isdiag) {
                #pragma unroll
                for (int q = 0; q < 4; q++) cvt_sts(bufBu[nb] + stsoff[q], rB[2 * q], rB[2 * q + 1]);
            }
            if (c + 2 < NCHUNKS) {
                #pragma unroll
                for (int i = 0; i < 8; i++) rA[i] = ((const float4*)(gAf + (c + 2) * KCH))[i];
            }
        }
        __syncthreads();
    }

    // ---------------- fused epilogue (dual-sided for off-diag tiles) --------
    const int qrow = lane >> 2;
    const int qcol = (lane & 3) * 2;

    int cl[8][2];
    #pragma unroll
    for (int nt = 0; nt < 8; nt++) {
        int j = wn * 64 + nt * 8 + qcol;
        cl[nt][0] = collab[j];
        cl[nt][1] = collab[j + 1];
    }

    float cpos[16], cneg[16];
    #pragma unroll
    for (int k = 0; k < 16; k++) { cpos[k] = 0.f; cneg[k] = 0.f; }

    #pragma unroll
    for (int mt = 0; mt < 2; mt++) {
        int r0 = wm * 32 + mt * 16 + qrow;
        int r1 = r0 + 8;
        int l0 = rowlab[r0], l1 = rowlab[r1];
        int ig0 = rowbase + r0, ig1 = rowbase + r1;
        float pos0 = 0.f, neg0 = 0.f, pos1 = 0.f, neg1 = 0.f;

        #pragma unroll
        for (int nt = 0; nt < 8; nt++) {
            int jg = colbase + wn * 64 + nt * 8 + qcol;
            #pragma unroll
            for (int e = 0; e < 2; e++) {
                float v0 = d[mt][nt][e];
                float v1 = d[mt][nt][2 + e];
                int lj = cl[nt][e];
                int jge = jg + e;
                bool eq0 = (lj == l0), eq1 = (lj == l1);
                float e0 = __expf(eq0 ? (0.5f - v0) : (10.0f * v0 - 5.0f));
                float e1 = __expf(eq1 ? (0.5f - v1) : (10.0f * v1 - 5.0f));
                if (eq0) { if (jge != ig0) pos0 += e0; } else neg0 += e0;
                if (eq1) { if (jge != ig1) pos1 += e1; } else neg1 += e1;
                if (!isdiag) {
                    int k = nt * 2 + e;
                    if (eq0) cpos[k] += e0; else cneg[k] += e0;
                    if (eq1) cpos[k] += e1; else cneg[k] += e1;
                }
            }
        }
        #pragma unroll
        for (int m = 1; m <= 2; m <<= 1) {
            pos0 += __shfl_xor_sync(0xFFFFFFFFu, pos0, m);
            neg0 += __shfl_xor_sync(0xFFFFFFFFu, neg0, m);
            pos1 += __shfl_xor_sync(0xFFFFFFFFu, pos1, m);
            neg1 += __shfl_xor_sync(0xFFFFFFFFu, neg1, m);
        }
        if ((lane & 3) == 0) {
            atomicAdd(&g_pos[ig0], pos0);
            atomicAdd(&g_neg[ig0], neg0);
            atomicAdd(&g_pos[ig1], pos1);
            atomicAdd(&g_neg[ig1], neg1);
        }
    }

    if (!isdiag) {
        #pragma unroll
        for (int k = 0; k < 16; k++) {
            #pragma unroll
            for (int m = 4; m <= 16; m <<= 1) {
                cpos[k] += __shfl_xor_sync(0xFFFFFFFFu, cpos[k], m);
                cneg[k] += __shfl_xor_sync(0xFFFFFFFFu, cneg[k], m);
            }
        }
        if (lane < 4) {
            #pragma unroll
            for (int nt = 0; nt < 8; nt++)
                #pragma unroll
                for (int e = 0; e < 2; e++) {
                    int j = colbase + wn * 64 + nt * 8 + lane * 2 + e;
                    atomicAdd(&g_pos[j], cpos[nt * 2 + e]);
                    atomicAdd(&g_neg[j], cneg[nt * 2 + e]);
                }
        }
    }
}

// ============================================================================
// Kernel 2: finalize — log1p terms, valid mask, mean (shfl-based)
// ============================================================================
__global__ void ms_finalize(float* __restrict__ out) {
    __shared__ float swp[32];
    __shared__ float swc[32];
    int t = threadIdx.x;
    int wid = t >> 5, lane = t & 31;
    float tot = 0.f, cnt = 0.f;
    for (int r = t; r < N_EMB; r += 1024) {
        float p = g_pos[r], q = g_neg[r];
        if (p > 0.f && q > 0.f) {
            tot += log1pf(p) + 0.1f * log1pf(q);
            cnt += 1.f;
        }
    }
    #pragma unroll
    for (int m = 16; m > 0; m >>= 1) {
        tot += __shfl_xor_sync(0xFFFFFFFFu, tot, m);
        cnt += __shfl_xor_sync(0xFFFFFFFFu, cnt, m);
    }
    if (lane == 0) { swp[wid] = tot; swc[wid] = cnt; }
    __syncthreads();
    if (wid == 0) {
        tot = swp[lane];
        cnt = swc[lane];
        #pragma unroll
        for (int m = 16; m > 0; m >>= 1) {
            tot += __shfl_xor_sync(0xFFFFFFFFu, tot, m);
            cnt += __shfl_xor_sync(0xFFFFFFFFu, cnt, m);
        }
        if (lane == 0) out[0] = cnt > 0.f ? tot / cnt : 0.f;
    }
}

// ============================================================================
extern "C" void kernel_launch(void* const* d_in, const int* in_sizes, int n_in,
                              void* d_out, int out_size) {
    const float* emb = (const float*)d_in[0];
    const void* labels = d_in[1];
    float* out = (float*)d_out;

    cudaFuncSetAttribute(ms_main, cudaFuncAttributeMaxDynamicSharedMemorySize, SM_TOTAL);

    ms_init<<<16, NTHREADS>>>(labels);
    ms_main<<<NTILES, NTHREADS, SM_TOTAL>>>(emb);
    ms_finalize<<<1, 1024>>>(out);
}

// round 9
// speedup vs baseline: 2.7941x; 2.7941x over previous
#include <cuda_runtime.h>
#include <cuda_bf16.h>
#include <cstdint>

// ============================================================================
// MultiSimilarityLoss on GB300 (sm_103a; PTX target compute_103 -> no tcgen05;
// mma.sync bf16 HMMA + ldmatrix + cp.async)
//   Upper-triangular 128x128 tiles of sim = E@E^T; dual-sided fused epilogue.
//   R9: single __syncthreads per K-chunk (wait -> sync -> issue -> mma),
//   2-stage buffers; otherwise identical to the proven R6 kernel.
// ============================================================================

#define N_EMB   4096
#define D_EMB   512
#define MTILE   128
#define NTILE   128
#define KCH     64            // K chunk (64 bf16 = 128B rows)
#define NCHUNKS (D_EMB / KCH) // 8
#define NTHREADS 256
#define NTB     (N_EMB / MTILE)          // 32
#define NTILES  (NTB * (NTB + 1) / 2)    // 528

// Scratch (no cudaMalloc allowed)
__device__ __nv_bfloat16 g_eb[N_EMB * D_EMB];
__device__ float g_pos[N_EMB];
__device__ float g_neg[N_EMB];
__device__ int   g_lab[N_EMB];

// smem: labels (1KB) + 2 double-buffered A/B tiles (4 x 16KB)
#define SM_LABELS  0
#define SM_TILES   1024
#define TILE_BYTES 16384                 // 128 rows x 128B
#define SM_TOTAL   (1024 + 4 * TILE_BYTES)  // 66560

__device__ __forceinline__ uint32_t smem_u32(const void* p) {
    uint32_t a;
    asm("{ .reg .u64 t; cvta.to.shared.u64 t, %1; cvt.u32.u64 %0, t; }" : "=r"(a) : "l"(p));
    return a;
}

__device__ __forceinline__ uint32_t sw128(uint32_t off) {
    return off ^ ((off >> 3) & 0x70);
}

__device__ __forceinline__ void ldsm_x4(uint32_t* r, uint32_t addr) {
    asm volatile("ldmatrix.sync.aligned.m8n8.x4.shared.b16 {%0,%1,%2,%3}, [%4];"
                 : "=r"(r[0]), "=r"(r[1]), "=r"(r[2]), "=r"(r[3]) : "r"(addr));
}

__device__ __forceinline__ void mma16816(float* d, const uint32_t* a, uint32_t b0, uint32_t b1) {
    asm volatile(
        "mma.sync.aligned.m16n8k16.row.col.f32.bf16.bf16.f32 "
        "{%0,%1,%2,%3}, {%4,%5,%6,%7}, {%8,%9}, {%0,%1,%2,%3};"
        : "+f"(d[0]), "+f"(d[1]), "+f"(d[2]), "+f"(d[3])
        : "r"(a[0]), "r"(a[1]), "r"(a[2]), "r"(a[3]), "r"(b0), "r"(b1));
}

__device__ __forceinline__ void cp16(uint32_t dst, const void* src) {
    asm volatile("cp.async.cg.shared.global [%0], [%1], 16;" :: "r"(dst), "l"(src));
}

// ============================================================================
// Kernel 0: prep — labels decode (block 0), fp32 -> bf16, resets
// ============================================================================
#define PREP_BLOCKS 512
__global__ void ms_prep(const float* __restrict__ emb, const void* __restrict__ rawlab) {
    int t = threadIdx.x;
    int g = blockIdx.x * NTHREADS + t;
    if (blockIdx.x == 0) {
        __shared__ int s_not64;
        const int* r32 = (const int*)rawlab;
        if (t == 0) s_not64 = 0;
        __syncthreads();
        int nz = 0;
        for (int i = t; i < N_EMB / 2; i += NTHREADS) nz |= r32[2 * i + 1];
        if (nz) atomicOr(&s_not64, 1);
        __syncthreads();
        if (s_not64 == 0) {
            const long long* r64 = (const long long*)rawlab;
            for (int i = t; i < N_EMB; i += NTHREADS) g_lab[i] = (int)r64[i];
        } else {
            for (int i = t; i < N_EMB; i += NTHREADS) g_lab[i] = r32[i];
        }
    }
    // 4 independent float4 loads per thread; 512*256*4 = 524288 = N*D/4 exact
    const int S = PREP_BLOCKS * NTHREADS;
    const float4* src = (const float4*)emb;
    __nv_bfloat162* dst = (__nv_bfloat162*)g_eb;
    float4 v0 = src[g];
    float4 v1 = src[g + S];
    float4 v2 = src[g + 2 * S];
    float4 v3 = src[g + 3 * S];
    dst[2 * g]               = __floats2bfloat162_rn(v0.x, v0.y);
    dst[2 * g + 1]           = __floats2bfloat162_rn(v0.z, v0.w);
    dst[2 * (g + S)]         = __floats2bfloat162_rn(v1.x, v1.y);
    dst[2 * (g + S) + 1]     = __floats2bfloat162_rn(v1.z, v1.w);
    dst[2 * (g + 2 * S)]     = __floats2bfloat162_rn(v2.x, v2.y);
    dst[2 * (g + 2 * S) + 1] = __floats2bfloat162_rn(v2.z, v2.w);
    dst[2 * (g + 3 * S)]     = __floats2bfloat162_rn(v3.x, v3.y);
    dst[2 * (g + 3 * S) + 1] = __floats2bfloat162_rn(v3.z, v3.w);
    if (g < N_EMB) { g_pos[g] = 0.f; g_neg[g] = 0.f; }
}

// ============================================================================
// Kernel 1: main — upper-triangular 128x128 tiles, dual-sided fused epilogue
// Single __syncthreads per chunk: [wait 0 -> sync -> issue c+1 -> mma c].
// Safety: the sync at iter c guarantees all warps finished iter c-1's MMA,
// so overwriting buffer (c+1)&1 == (c-1)&1 is race-free.
// ============================================================================
__global__ __launch_bounds__(NTHREADS, 2) void ms_main() {
    extern __shared__ char smem[];
    int* collab = (int*)(smem + SM_LABELS);        // 128 ints
    int* rowlab = (int*)(smem + SM_LABELS + 512);  // 128 ints
    char* tiles = smem + SM_TILES;

    // decode linear tile id -> (by, bx) with bx >= by (row-major triangle)
    int rem = blockIdx.x;
    int by = 0;
    while (rem >= (NTB - by)) { rem -= (NTB - by); by++; }
    int bx = by + rem;
    const bool isdiag = (bx == by);

    const int tid  = threadIdx.x;
    const int wid  = tid >> 5;
    const int lane = tid & 31;
    const int wm   = wid & 3;   // M offset wm*32
    const int wn   = wid >> 2;  // N offset wn*64
    const int colbase = bx * NTILE;
    const int rowbase = by * MTILE;

    if (tid < 128) collab[tid] = g_lab[colbase + tid];
    else           rowlab[tid - 128] = g_lab[rowbase + tid - 128];

    const __nv_bfloat16* gA = g_eb + (size_t)rowbase * D_EMB;
    const __nv_bfloat16* gB = g_eb + (size_t)colbase * D_EMB;

    // loader mapping (per thread): 2 x 16B per tile per chunk
    const int ldrow = tid >> 3;          // 0..31 base row
    const int ldseg = tid & 7;           // 16B segment
    const uint32_t lo0 = sw128((uint32_t)(ldrow * 128 + ldseg * 16));

    // ---- issue chunk 0 loads ----
    {
        uint32_t abuf = smem_u32(tiles);
        #pragma unroll
        for (int i = 0; i < 4; i++) {
            int row = ldrow + i * 32;
            uint32_t off = lo0 + i * 4096;
            cp16(abuf + off, gA + (size_t)row * D_EMB + ldseg * 8);
            cp16(abuf + TILE_BYTES + off, gB + (size_t)row * D_EMB + ldseg * 8);
        }
        asm volatile("cp.async.commit_group;" ::: "memory");
    }

    float d[2][8][4];
    #pragma unroll
    for (int mt = 0; mt < 2; mt++)
        #pragma unroll
        for (int nt = 0; nt < 8; nt++)
            #pragma unroll
            for (int r = 0; r < 4; r++) d[mt][nt][r] = 0.f;

    const int lrow = (lane & 7) + ((lane >> 3) & 1) * 8;
    const int lkh  = (lane >> 4) * 16;

    for (int c = 0; c < NCHUNKS; c++) {
        asm volatile("cp.async.wait_group 0;" ::: "memory");   // chunk c landed
        __syncthreads();   // all warps see chunk c; all warps done reading c-1

        if (c + 1 < NCHUNKS) {
            uint32_t abuf = smem_u32(tiles + ((c + 1) & 1) * 2 * TILE_BYTES);
            const __nv_bfloat16* pA = gA + (c + 1) * KCH;
            const __nv_bfloat16* pB = gB + (c + 1) * KCH;
            #pragma unroll
            for (int i = 0; i < 4; i++) {
                int row = ldrow + i * 32;
                uint32_t off = lo0 + i * 4096;
                cp16(abuf + off, pA + (size_t)row * D_EMB + ldseg * 8);
                cp16(abuf + TILE_BYTES + off, pB + (size_t)row * D_EMB + ldseg * 8);
            }
            asm volatile("cp.async.commit_group;" ::: "memory");
        }

        uint32_t abase = smem_u32(tiles + (c & 1) * 2 * TILE_BYTES);
        uint32_t bbase = abase + TILE_BYTES;

        #pragma unroll
        for (int s = 0; s < 4; s++) {
            uint32_t kb = s * 32;
            uint32_t a[2][4];
            #pragma unroll
            for (int mt = 0; mt < 2; mt++) {
                int row = wm * 32 + mt * 16 + lrow;
                ldsm_x4(a[mt], abase + sw128(row * 128 + kb + lkh));
            }
            uint32_t bq[4][4];
            #pragma unroll
            for (int nt2 = 0; nt2 < 4; nt2++) {
                int row = wn * 64 + nt2 * 16 + lrow;
                ldsm_x4(bq[nt2], bbase + sw128(row * 128 + kb + lkh));
            }
            #pragma unroll
            for (int mt = 0; mt < 2; mt++)
                #pragma unroll
                for (int nt = 0; nt < 8; nt++) {
                    int nt2 = nt >> 1, odd = nt & 1;
                    mma16816(d[mt][nt], a[mt], bq[nt2][odd], bq[nt2][odd + 2]);
                }
        }
    }

    // ---------------- fused epilogue (dual-sided for off-diag tiles) --------
    const int qrow = lane >> 2;
    const int qcol = (lane & 3) * 2;

    int cl[8][2];
    #pragma unroll
    for (int nt = 0; nt < 8; nt++) {
        int j = wn * 64 + nt * 8 + qcol;
        cl[nt][0] = collab[j];
        cl[nt][1] = collab[j + 1];
    }

    float cpos[16], cneg[16];
    #pragma unroll
    for (int k = 0; k < 16; k++) { cpos[k] = 0.f; cneg[k] = 0.f; }

    #pragma unroll
    for (int mt = 0; mt < 2; mt++) {
        int r0 = wm * 32 + mt * 16 + qrow;
        int r1 = r0 + 8;
        int l0 = rowlab[r0], l1 = rowlab[r1];
        int ig0 = rowbase + r0, ig1 = rowbase + r1;
        float pos0 = 0.f, neg0 = 0.f, pos1 = 0.f, neg1 = 0.f;

        #pragma unroll
        for (int nt = 0; nt < 8; nt++) {
            int jg = colbase + wn * 64 + nt * 8 + qcol;
            #pragma unroll
            for (int e = 0; e < 2; e++) {
                float v0 = d[mt][nt][e];
                float v1 = d[mt][nt][2 + e];
                int lj = cl[nt][e];
                int jge = jg + e;
                bool eq0 = (lj == l0), eq1 = (lj == l1);
                float e0 = __expf(eq0 ? (0.5f - v0) : (10.0f * v0 - 5.0f));
                float e1 = __expf(eq1 ? (0.5f - v1) : (10.0f * v1 - 5.0f));
                if (eq0) { if (jge != ig0) pos0 += e0; } else neg0 += e0;
                if (eq1) { if (jge != ig1) pos1 += e1; } else neg1 += e1;
                if (!isdiag) {
                    int k = nt * 2 + e;
                    if (eq0) cpos[k] += e0; else cneg[k] += e0;
                    if (eq1) cpos[k] += e1; else cneg[k] += e1;
                }
            }
        }
        #pragma unroll
        for (int m = 1; m <= 2; m <<= 1) {
            pos0 += __shfl_xor_sync(0xFFFFFFFFu, pos0, m);
            neg0 += __shfl_xor_sync(0xFFFFFFFFu, neg0, m);
            pos1 += __shfl_xor_sync(0xFFFFFFFFu, pos1, m);
            neg1 += __shfl_xor_sync(0xFFFFFFFFu, neg1, m);
        }
        if ((lane & 3) == 0) {
            atomicAdd(&g_pos[ig0], pos0);
            atomicAdd(&g_neg[ig0], neg0);
            atomicAdd(&g_pos[ig1], pos1);
            atomicAdd(&g_neg[ig1], neg1);
        }
    }

    if (!isdiag) {
        #pragma unroll
        for (int k = 0; k < 16; k++) {
            #pragma unroll
            for (int m = 4; m <= 16; m <<= 1) {
                cpos[k] += __shfl_xor_sync(0xFFFFFFFFu, cpos[k], m);
                cneg[k] += __shfl_xor_sync(0xFFFFFFFFu, cneg[k], m);
            }
        }
        if (lane < 4) {
            #pragma unroll
            for (int nt = 0; nt < 8; nt++)
                #pragma unroll
                for (int e = 0; e < 2; e++) {
                    int j = colbase + wn * 64 + nt * 8 + lane * 2 + e;
                    atomicAdd(&g_pos[j], cpos[nt * 2 + e]);
                    atomicAdd(&g_neg[j], cneg[nt * 2 + e]);
                }
        }
    }
}

// ============================================================================
// Kernel 2: finalize — log1p terms, valid mask, mean (shfl-based)
// ============================================================================
__global__ void ms_finalize(float* __restrict__ out) {
    __shared__ float swp[32];
    __shared__ float swc[32];
    int t = threadIdx.x;
    int wid = t >> 5, lane = t & 31;
    float tot = 0.f, cnt = 0.f;
    for (int r = t; r < N_EMB; r += 1024) {
        float p = g_pos[r], q = g_neg[r];
        if (p > 0.f && q > 0.f) {
            tot += log1pf(p) + 0.1f * log1pf(q);
            cnt += 1.f;
        }
    }
    #pragma unroll
    for (int m = 16; m > 0; m >>= 1) {
        tot += __shfl_xor_sync(0xFFFFFFFFu, tot, m);
        cnt += __shfl_xor_sync(0xFFFFFFFFu, cnt, m);
    }
    if (lane == 0) { swp[wid] = tot; swc[wid] = cnt; }
    __syncthreads();
    if (wid == 0) {
        tot = swp[lane];
        cnt = swc[lane];
        #pragma unroll
        for (int m = 16; m > 0; m >>= 1) {
            tot += __shfl_xor_sync(0xFFFFFFFFu, tot, m);
            cnt += __shfl_xor_sync(0xFFFFFFFFu, cnt, m);
        }
        if (lane == 0) out[0] = cnt > 0.f ? tot / cnt : 0.f;
    }
}

// ============================================================================
extern "C" void kernel_launch(void* const* d_in, const int* in_sizes, int n_in,
                              void* d_out, int out_size) {
    const float* emb = (const float*)d_in[0];
    const void* labels = d_in[1];
    float* out = (float*)d_out;

    cudaFuncSetAttribute(ms_main, cudaFuncAttributeMaxDynamicSharedMemorySize, SM_TOTAL);

    ms_prep<<<PREP_BLOCKS, NTHREADS>>>(emb, labels);
    ms_main<<<NTILES, NTHREADS, SM_TOTAL>>>();
    ms_finalize<<<1, 1024>>>(out);
}